// round 16
// baseline (speedup 1.0000x reference)
#include <cuda_runtime.h>
#include <math.h>

#define NN      3072
#define TWO_N   6144
#define DIM     128
#define SEQ     16
#define EE      196608
#define CC      100
#define HH      4
#define HD      32
#define INV_SQRT_HD 0.17677669529663687f
#define DELTA_T 0.1f
#define PRESERVE 0.1f

#define OUT_CAT   0
#define OUT_SKILL (TWO_N * DIM)
#define OUT_PRED  (2 * TWO_N * DIM)
#define OUT_LOSS  (2 * TWO_N * DIM + TWO_N * TWO_N)

// ----------------------------- device scratch -----------------------------
__device__ float g_dsum[DIM];
__device__ float g_ssum[DIM];
__device__ float g_fused[(size_t)TWO_N * DIM];
__device__ float g_s1[(size_t)TWO_N * DIM];
__device__ float g_s2[(size_t)TWO_N * DIM];
__device__ float g_scores[(size_t)TWO_N * TWO_N];   // general path only
__device__ float g_deg[TWO_N];
__device__ float g_degsp[TWO_N];
__device__ float g_xw[(size_t)TWO_N * DIM];     // dense chain
__device__ float g_xw2[(size_t)TWO_N * DIM];    // sparse chain
__device__ float g_agg[(size_t)TWO_N * DIM];
__device__ float g_tmpA[(size_t)TWO_N * DIM];
__device__ float g_tmpB[(size_t)TWO_N * DIM];
__device__ float g_emb[(size_t)TWO_N * DIM];
__device__ float g_sm[(size_t)TWO_N * CC];
__device__ float g_pooled[CC * DIM];
__device__ float g_G[CC * CC];
__device__ float g_kp2[CC * DIM];
__device__ float g_vp2[CC * DIM];
__device__ float g_qp2[(size_t)TWO_N * DIM];
__device__ float g_wt[DIM * DIM];
__device__ float g_acc[8];   // [0]=||A||^2 [1]=<A,SS^T> [2]=ent_sum
__device__ int   g_flag;

// MHA1 chain buffers
__device__ float g_qv[(size_t)TWO_N * DIM];
__device__ float g_U[(size_t)TWO_N * 4 * DIM];         // [2N, 512]
__device__ float g_cq[(size_t)TWO_N * 640];            // [skill(128) | c(512)] per row
__device__ float g_Zcat[4 * DIM * DIM];                // [512, 128]
__device__ float g_zb[DIM];
__device__ float g_Wcomb[DIM * 4 * DIM];               // [128, 512]
__device__ float g_Ub[4 * DIM];                        // [512]
__device__ float g_vqb[DIM * HH];                      // [128][4]
__device__ float g_cb[HH];
__device__ float g_wbig[640 * DIM];                    // [Wf_top(128); Zf(512)] x 128
__device__ float g_fb[DIM];

// CSR for sparse GCN (+ raw weights for link loss)
__device__ int   g_csr_cnt[TWO_N];
__device__ int   g_csr_off[TWO_N + 1];
__device__ int   g_csr_src[EE];
__device__ float g_csr_coef[EE];
__device__ float g_csr_w[EE];

// ----------------------------- helpers -----------------------------
__device__ __forceinline__ float blockReduceSum(float v, float* sh) {
    int t = threadIdx.x;
    sh[t] = v; __syncthreads();
    for (int s = blockDim.x >> 1; s > 0; s >>= 1) {
        if (t < s) sh[t] += sh[t + s];
        __syncthreads();
    }
    float r = sh[0]; __syncthreads();
    return r;
}
__device__ __forceinline__ float blockReduceMax(float v, float* sh) {
    int t = threadIdx.x;
    sh[t] = v; __syncthreads();
    for (int s = blockDim.x >> 1; s > 0; s >>= 1) {
        if (t < s) sh[t] = fmaxf(sh[t], sh[t + s]);
        __syncthreads();
    }
    float r = sh[0]; __syncthreads();
    return r;
}

// ---------------- SGEMM device block-function: 64x128 tile, 8x4/thread, double-buffered ----------
__device__ void sgemm_block(const float* __restrict__ A, const float* __restrict__ B,
                            const float* __restrict__ bias, float* __restrict__ Cmat,
                            int M, int Nn, int K, int lda, int ldc, int bmi, int bni) {
    __shared__ float As[2][16][65];
    __shared__ float Bs[2][16][128];
    int bm = bmi * 64;
    int bn = bni * 128;
    int tid = threadIdx.x;
    int tr = tid >> 5, tc = tid & 31;
    float acc[8][4];
    #pragma unroll
    for (int r = 0; r < 8; r++)
        #pragma unroll
        for (int c = 0; c < 4; c++) acc[r][c] = 0.f;

    #pragma unroll
    for (int j = 0; j < 4; j++) {
        int idx = tid + 256 * j;
        int m = idx >> 4, kk = idx & 15;
        int row = bm + m; if (row >= M) row = M - 1;
        As[0][kk][m] = A[(size_t)row * lda + kk];
    }
    #pragma unroll
    for (int j = 0; j < 8; j++) {
        int idx = tid + 256 * j;
        int kk = idx >> 7, n = idx & 127;
        Bs[0][kk][n] = (bn + n < Nn) ? B[(size_t)kk * Nn + bn + n] : 0.f;
    }
    __syncthreads();

    int buf = 0;
    for (int k0 = 0; k0 < K; k0 += 16) {
        int nb = buf ^ 1;
        if (k0 + 16 < K) {
            #pragma unroll
            for (int j = 0; j < 4; j++) {
                int idx = tid + 256 * j;
                int m = idx >> 4, kk = idx & 15;
                int row = bm + m; if (row >= M) row = M - 1;
                As[nb][kk][m] = A[(size_t)row * lda + k0 + 16 + kk];
            }
            #pragma unroll
            for (int j = 0; j < 8; j++) {
                int idx = tid + 256 * j;
                int kk = idx >> 7, n = idx & 127;
                Bs[nb][kk][n] = (bn + n < Nn) ? B[(size_t)(k0 + 16 + kk) * Nn + bn + n] : 0.f;
            }
        }
        #pragma unroll
        for (int kk = 0; kk < 16; kk++) {
            float4 b4 = *reinterpret_cast<const float4*>(&Bs[buf][kk][tc * 4]);
            #pragma unroll
            for (int r = 0; r < 8; r++) {
                float a = As[buf][kk][tr * 8 + r];
                acc[r][0] += a * b4.x; acc[r][1] += a * b4.y;
                acc[r][2] += a * b4.z; acc[r][3] += a * b4.w;
            }
        }
        __syncthreads();
        buf = nb;
    }
    #pragma unroll
    for (int r = 0; r < 8; r++) {
        int m = bm + tr * 8 + r;
        if (m >= M) continue;
        #pragma unroll
        for (int c = 0; c < 4; c++) {
            int n = bn + tc * 4 + c;
            if (n < Nn) {
                float v = acc[r][c];
                if (bias) v += bias[n];
                Cmat[(size_t)m * ldc + n] = v;
            }
        }
    }
}

__global__ void k_sgemm(const float* __restrict__ A, const float* __restrict__ B,
                        const float* __restrict__ bias, float* __restrict__ Cmat,
                        int M, int Nn, int K, int ldc) {
    sgemm_block(A, B, bias, Cmat, M, Nn, K, K, ldc, blockIdx.y, blockIdx.x);
}

// ----------------------------- init -----------------------------
__global__ void k_init(const float* __restrict__ sender, const float* __restrict__ receiver) {
    int i = blockIdx.x * blockDim.x + threadIdx.x;
    if (i < TWO_N) { g_deg[i] = 1.0f; g_degsp[i] = 1.0f; g_csr_cnt[i] = 0; }
    if (i < CC * DIM) g_pooled[i] = 0.f;
    if (i < CC * CC) g_G[i] = 0.f;
    if (i < 2 * DIM) (i < DIM ? g_dsum : g_ssum)[i & 127] = 0.f;
    if (i < 8) g_acc[i] = 0.f;
    if (i == 0) g_flag = (sender[0] == receiver[0]) ? 1 : 0;
}

// ----------------------------- stage1: prep + seqsum + edge1 + predg_zero -------------------------
__global__ void k_stage1(const float* __restrict__ m1wi, const float* __restrict__ m1wo,
                         const float* __restrict__ m1bo, const float* __restrict__ m1bi,
                         const float* __restrict__ m2wi,
                         const float* __restrict__ demand, const float* __restrict__ supply,
                         const int* __restrict__ dst, const float* __restrict__ w,
                         float* __restrict__ out_pred) {
    int b = blockIdx.x;
    int t = threadIdx.x;  // 256
    if (b < 256) {                        // Zcat
        int i = b * 256 + t;
        int row = i >> 7, tt = i & 127;
        int h = row >> 7, d = row & 127;
        const float* wv = m1wi + (size_t)2 * DIM * DIM;
        float acc = 0.f;
        #pragma unroll 8
        for (int j = 0; j < 32; j++)
            acc += m1wo[(size_t)tt * DIM + h * 32 + j] * wv[(size_t)(h * 32 + j) * DIM + d];
        g_Zcat[(size_t)row * DIM + tt] = acc;
    } else if (b == 256) {                // zb
        if (t < DIM) {
            const float* bv = m1bi + 2 * DIM;
            float acc = m1bo[t];
            #pragma unroll 8
            for (int k = 0; k < DIM; k++) acc += m1wo[(size_t)t * DIM + k] * bv[k];
            g_zb[t] = acc;
        }
    } else if (b < 321) {                 // m2wi transpose (64)
        int i = (b - 257) * 256 + t;
        int n = i >> 7, k = i & 127;
        g_wt[(size_t)k * DIM + n] = m2wi[(size_t)n * DIM + k];
    } else if (b < 369) {                 // seqsum (48)
        if (t < DIM) {
            int sb = b - 321;
            int tensor = sb / 24, chunk = sb % 24;
            const float* base = tensor ? supply : demand;
            float acc = 0.f;
            int n0 = chunk * 128;
            for (int n = n0; n < n0 + 128; n++)
                acc += base[(size_t)n * SEQ * DIM + (size_t)(SEQ - 1) * DIM + t];
            atomicAdd(&(tensor ? g_ssum : g_dsum)[t], acc);
        }
    } else if (b < 1137) {                // edge1 (768)
        int e = (b - 369) * 256 + t;
        if (e < EE) {
            int q = dst[e];
            atomicAdd(&g_degsp[q], w[e]);
            atomicAdd(&g_csr_cnt[q], 1);
        }
    } else if (b < 1393) {                // Wcomb (256): [128,512]
        int i = (b - 1137) * 256 + t;
        int k = i >> 9, col = i & 511;
        int h = col >> 7, d = col & 127;
        const float* wk = m1wi + (size_t)DIM * DIM;
        float acc = 0.f;
        #pragma unroll 8
        for (int j = 0; j < 32; j++)
            acc += m1wi[(size_t)(h * 32 + j) * DIM + k] * wk[(size_t)(h * 32 + j) * DIM + d];
        g_Wcomb[(size_t)k * 512 + col] = acc;
    } else if (b == 1393) {               // vqb [128][4]
        for (int i = t; i < DIM * HH; i += 256) {
            int k = i >> 2, h = i & 3;
            const float* bk = m1bi + DIM;
            float acc = 0.f;
            #pragma unroll 8
            for (int j = 0; j < 32; j++)
                acc += m1wi[(size_t)(h * 32 + j) * DIM + k] * bk[h * 32 + j];
            g_vqb[i] = acc;
        }
    } else if (b == 1394) {               // Ub [512] + cb[4]
        const float* wk = m1wi + (size_t)DIM * DIM;
        const float* bk = m1bi + DIM;
        for (int col = t; col < 512; col += 256) {
            int h = col >> 7, d = col & 127;
            float acc = 0.f;
            #pragma unroll 8
            for (int j = 0; j < 32; j++)
                acc += m1bi[h * 32 + j] * wk[(size_t)(h * 32 + j) * DIM + d];
            g_Ub[col] = acc;
        }
        if (t < HH) {
            float acc = 0.f;
            for (int j = 0; j < 32; j++) acc += m1bi[t * 32 + j] * bk[t * 32 + j];
            g_cb[t] = acc;
        }
    } else {                              // predg zero-fill (flag path) (2048)
        if (!g_flag) return;
        float4 z = make_float4(0.f, 0.f, 0.f, 0.f);
        float4* o = reinterpret_cast<float4*>(out_pred);
        size_t total = (size_t)TWO_N * TWO_N / 4;
        for (size_t j = (size_t)(b - 1395) * 256 + t; j < total; j += (size_t)2048 * 256)
            o[j] = z;
    }
}

// ----------------------------- stage2: scan (b0) + qv (merged, 1024 threads) ----------------------
__global__ void k_stage2(const float* __restrict__ skill, float* __restrict__ out_cat) {
    int b = blockIdx.x;
    int t = threadIdx.x;  // 1024
    if (b == 0) {         // scan
        __shared__ int sh[1024];
        int base = t * 6;
        int loc[6];
        int s = 0;
        #pragma unroll
        for (int k = 0; k < 6; k++) { loc[k] = s; s += g_csr_cnt[base + k]; }
        sh[t] = s;
        __syncthreads();
        for (int off = 1; off < 1024; off <<= 1) {
            int add = (t >= off) ? sh[t - off] : 0;
            __syncthreads();
            sh[t] += add;
            __syncthreads();
        }
        int excl = sh[t] - s;
        #pragma unroll
        for (int k = 0; k < 6; k++) {
            int o = excl + loc[k];
            g_csr_off[base + k] = o;
            g_csr_cnt[base + k] = o;
        }
        if (t == 1023) g_csr_off[TWO_N] = sh[1023];
    } else {              // qv + cq skill half + out_cat
        int i = (b - 1) * 1024 + t;
        int bb = i >> 7, tt = i & 127;
        bool dem = bb < NN;
        int idx = dem ? bb : bb - NN;
        float sv = skill[(size_t)idx * DIM + tt];
        g_qv[i] = sv + (dem ? g_dsum : g_ssum)[tt];
        g_cq[(size_t)bb * 640 + tt] = sv;
        out_cat[i] = sv;
    }
}

// ----------------------------- stage3: Wtop + Zf GEMM + fb + U GEMM -------------------------------
__global__ void k_stage3(const float* __restrict__ w_fuse, const float* __restrict__ b_fuse) {
    int b = blockIdx.x;
    int t = threadIdx.x;  // 256
    if (b < 64) {             // Wtop copy
        int i = b * 256 + t;
        g_wbig[i] = w_fuse[i];
    } else if (b < 72) {      // Zf = Zcat @ Wf_bot -> wbig rows 128..639
        sgemm_block(g_Zcat, w_fuse + (size_t)DIM * DIM, nullptr, g_wbig + (size_t)DIM * DIM,
                    512, DIM, DIM, DIM, DIM, b - 64, 0);
    } else if (b == 72) {     // fb
        if (t < DIM) {
            float acc = b_fuse[t];
            #pragma unroll 8
            for (int k = 0; k < DIM; k++) acc += g_zb[k] * w_fuse[(size_t)(DIM + k) * DIM + t];
            g_fb[t] = acc;
        }
    } else {                  // U = qv @ Wcomb + Ub (384 blocks)
        int idx = b - 73;
        sgemm_block(g_qv, g_Wcomb, g_Ub, g_U, TWO_N, 4 * DIM, DIM, DIM, 4 * DIM,
                    idx % 96, idx / 96);
    }
}

// ----------------------------- attn1 + fillcsr (merged, 128 threads) ------------------------------
__global__ void k_attn1(const float* __restrict__ demand, const float* __restrict__ supply,
                        const int* __restrict__ src, const int* __restrict__ dst,
                        const float* __restrict__ w) {
    int b = blockIdx.x;
    int t = threadIdx.x;  // 128
    if (b >= TWO_N) {     // fillcsr
        int e = (b - TWO_N) * 128 + t;
        if (e < EE) {
            int s = src[e], q = dst[e];
            float we = w[e];
            int pos = atomicAdd(&g_csr_cnt[q], 1);
            g_csr_src[pos] = s;
            g_csr_coef[pos] = rsqrtf(g_degsp[s]) * rsqrtf(g_degsp[q]) * we;
            g_csr_w[pos] = we;
        }
        return;
    }
    int wd = t >> 5, lane = t & 31;
    bool dem = b < NN;
    int idx = dem ? b : b - NN;
    const float* seq = (dem ? demand : supply) + (size_t)idx * SEQ * DIM;

    __shared__ float sh_seq[SEQ][DIM + 1];
    __shared__ float sh_U[HH][DIM];
    __shared__ float sh_p[HH][SEQ];

    for (int i = t; i < SEQ * DIM; i += 128) sh_seq[i >> 7][i & 127] = seq[i];
    for (int i = t; i < HH * DIM; i += 128) sh_U[i >> 7][i & 127] = g_U[(size_t)b * 512 + i];
    __syncthreads();

    float qb = 0.f;
    #pragma unroll
    for (int m = 0; m < 4; m++) {
        int k = lane + 32 * m;
        qb += g_qv[(size_t)b * DIM + k] * g_vqb[k * HH + wd];
    }
    #pragma unroll
    for (int o = 16; o > 0; o >>= 1) qb += __shfl_xor_sync(0xffffffff, qb, o);
    qb += g_cb[wd];

    float myl = -1e30f;
    if (lane < SEQ) {
        float acc = 0.f;
        #pragma unroll 16
        for (int d = 0; d < DIM; d++) acc += sh_U[wd][d] * sh_seq[lane][d];
        myl = (acc + qb) * INV_SQRT_HD;
    }
    float mx = myl;
    #pragma unroll
    for (int o = 8; o > 0; o >>= 1) mx = fmaxf(mx, __shfl_xor_sync(0xffffffff, mx, o));
    float e = (lane < SEQ) ? expf(myl - mx) : 0.f;
    float sm = e;
    #pragma unroll
    for (int o = 8; o > 0; o >>= 1) sm += __shfl_xor_sync(0xffffffff, sm, o);
    if (lane < SEQ) sh_p[wd][lane] = e / sm;
    __syncthreads();

    #pragma unroll
    for (int k = 0; k < 4; k++) {
        int d = lane + 32 * k;
        float acc = 0.f;
        #pragma unroll
        for (int s = 0; s < SEQ; s++) acc += sh_p[wd][s] * sh_seq[s][d];
        g_cq[(size_t)b * 640 + 128 + wd * DIM + d] = acc;
    }
}

// ----------------------------- stage8: tanhprep + dense-l0 GEMM + sparse-l0 GEMM -------------------
__global__ void k_stage8(const float* __restrict__ sender, const float* __restrict__ receiver,
                         const float* __restrict__ W0, const float* __restrict__ W1) {
    int b = blockIdx.x;
    if (b < 3072) {
        if (g_flag) return;
        int i = b * 256 + threadIdx.x;
        float f = g_fused[i];
        g_s1[i] = tanhf(sender[0] * f);
        g_s2[i] = tanhf(receiver[0] * f);
    } else if (b < 3168) {
        sgemm_block(g_fused, W0, nullptr, g_xw, TWO_N, DIM, DIM, DIM, DIM, b - 3072, 0);
    } else {
        sgemm_block(g_fused, W1, nullptr, g_xw2, TWO_N, DIM, DIM, DIM, DIM, b - 3168, 0);
    }
}

// ----------------------------- scores (general path; grid-stride) -----------------------------
__global__ void k_scores() {
    if (g_flag) return;
    __shared__ float A1[16][DIM], A2[16][DIM], B1[16][DIM], B2[16][DIM];
    int t = threadIdx.x;  // 256
    const int TILES = TWO_N / 16;
    for (int tile = blockIdx.x; tile < TILES * TILES; tile += gridDim.x) {
        int i0 = (tile / TILES) * 16, j0 = (tile % TILES) * 16;
        __syncthreads();
        for (int j = 0; j < 8; j++) {
            int idx = t + 256 * j;
            int r = idx >> 7, c = idx & 127;
            A1[r][c] = g_s1[(size_t)(i0 + r) * DIM + c];
            A2[r][c] = g_s2[(size_t)(i0 + r) * DIM + c];
            B1[r][c] = g_s1[(size_t)(j0 + r) * DIM + c];
            B2[r][c] = g_s2[(size_t)(j0 + r) * DIM + c];
        }
        __syncthreads();
        int ti = t >> 4, tj = t & 15;
        float acc = 0.f;
        for (int k = 0; k < DIM; k++)
            acc += A1[ti][k] * B2[tj][k] - A2[ti][k] * B1[tj][k];
        g_scores[(size_t)(i0 + ti) * TWO_N + j0 + tj] = acc;
    }
}

// ----------------------------- predg general (softmax+threshold+deg) ------------------------------
__global__ void k_predg_general(float* __restrict__ out_pred) {
    if (g_flag) return;
    int row = blockIdx.x;
    int t = threadIdx.x;  // 256
    __shared__ float sh[256];
    float* sr = g_scores + (size_t)row * TWO_N;
    float mx = 0.f;
    for (int i = t; i < TWO_N; i += 256) mx = fmaxf(mx, fmaxf(sr[i], 0.f));
    mx = blockReduceMax(mx, sh);
    float sum = 0.f;
    for (int i = t; i < TWO_N; i += 256) sum += expf(fmaxf(sr[i], 0.f) - mx);
    sum = blockReduceSum(sum, sh);
    float inv = 1.f / sum;
    for (int i = t; i < TWO_N; i += 256) {
        float p = expf(fmaxf(sr[i], 0.f) - mx) * inv;
        float pr = fmaxf(p - DELTA_T, 0.f);
        sr[i] = pr;
        out_pred[(size_t)row * TWO_N + i] = pr;
        if (pr != 0.f) atomicAdd(&g_deg[i], pr);
    }
}

// ----------------------------- dense agg (general path) -----------------------------
__global__ void k_dense_agg() {
    if (g_flag) return;
    int i0 = blockIdx.x * 32;
    int t = threadIdx.x;  // 256
    __shared__ float pcol[32];
    __shared__ float xrow[DIM];
    int dbase = t & 127, half = t >> 7;
    float acc[16];
    #pragma unroll
    for (int r = 0; r < 16; r++) acc[r] = 0.f;
    for (int j = 0; j < TWO_N; j++) {
        if (t < 32) pcol[t] = g_scores[(size_t)j * TWO_N + i0 + t];
        else if (t >= 128 && t < 256) {
            float sj = rsqrtf(g_deg[j]);
            xrow[t - 128] = sj * g_xw[(size_t)j * DIM + (t - 128)];
        }
        __syncthreads();
        #pragma unroll
        for (int r = 0; r < 16; r++) acc[r] += pcol[half + 2 * r] * xrow[dbase];
        __syncthreads();
    }
    #pragma unroll
    for (int r = 0; r < 16; r++) {
        int i = i0 + half + 2 * r;
        float di = rsqrtf(g_deg[i]);
        g_agg[(size_t)i * DIM + dbase] = acc[r] + di * g_xw[(size_t)i * DIM + dbase];
    }
}

// ---------------- device bodies: float4 dense combine / sparse gather ----------------
__device__ __forceinline__ float4 dense_combine_val4(int i4, const float* __restrict__ prev,
                                                     const float* __restrict__ b0, int layer) {
    int i = i4 * 4;
    int row = i >> 7, cb = i & 127;
    float di = rsqrtf(g_deg[row]);
    const float4* xw4 = reinterpret_cast<const float4*>(g_xw);
    const float4* agg4 = reinterpret_cast<const float4*>(g_agg);
    float4 v;
    if (g_flag) {
        float s = di * di;
        float4 x = xw4[i4];
        v = make_float4(s * x.x, s * x.y, s * x.z, s * x.w);
    } else {
        float4 a = agg4[i4];
        v = make_float4(di * a.x, di * a.y, di * a.z, di * a.w);
    }
    const float4* b4p = reinterpret_cast<const float4*>(b0 + layer * DIM + cb);
    float4 bb = *b4p;
    const float4* p4 = reinterpret_cast<const float4*>(prev);
    float4 pv = p4[i4];
    float4 r;
    r.x = (1.f - PRESERVE) * (v.x + bb.x) + PRESERVE * pv.x;
    r.y = (1.f - PRESERVE) * (v.y + bb.y) + PRESERVE * pv.y;
    r.z = (1.f - PRESERVE) * (v.z + bb.z) + PRESERVE * pv.z;
    r.w = (1.f - PRESERVE) * (v.w + bb.w) + PRESERVE * pv.w;
    return r;
}
__device__ __forceinline__ float4 spgather_val4(int q, int c4, const float* __restrict__ xw,
                                                const float* __restrict__ prev,
                                                const float* __restrict__ b1, int layer) {
    const float4* xw4 = reinterpret_cast<const float4*>(xw);
    float dv = rsqrtf(g_degsp[q]);
    float s0c = dv * dv;
    float4 x0 = xw4[(size_t)q * 32 + c4];
    float4 acc = make_float4(s0c * x0.x, s0c * x0.y, s0c * x0.z, s0c * x0.w);
    int beg = g_csr_off[q], end = g_csr_off[q + 1];
    for (int j = beg; j < end; j++) {
        float cf = g_csr_coef[j];
        int s = g_csr_src[j];
        float4 x = xw4[(size_t)s * 32 + c4];
        acc.x += cf * x.x; acc.y += cf * x.y; acc.z += cf * x.z; acc.w += cf * x.w;
    }
    const float4* b4p = reinterpret_cast<const float4*>(b1 + layer * DIM + c4 * 4);
    float4 bb = *b4p;
    const float4* p4 = reinterpret_cast<const float4*>(prev);
    float4 pv = p4[(size_t)q * 32 + c4];
    float4 r;
    r.x = (1.f - PRESERVE) * (acc.x + bb.x) + PRESERVE * pv.x;
    r.y = (1.f - PRESERVE) * (acc.y + bb.y) + PRESERVE * pv.y;
    r.z = (1.f - PRESERVE) * (acc.z + bb.z) + PRESERVE * pv.z;
    r.w = (1.f - PRESERVE) * (acc.w + bb.w) + PRESERVE * pv.w;
    return r;
}

// stage12: dense_combine l0 (float4) + spgather l0 (float4, 8 nodes/block)
__global__ void k_stage12(const float* __restrict__ b0, const float* __restrict__ b1) {
    int b = blockIdx.x;
    int t = threadIdx.x;  // 256
    if (b < 768) {
        int i4 = b * 256 + t;
        reinterpret_cast<float4*>(g_tmpA)[i4] = dense_combine_val4(i4, g_fused, b0, 0);
    } else {
        int q = (b - 768) * 8 + (t >> 5);
        int c4 = t & 31;
        reinterpret_cast<float4*>(g_tmpB)[(size_t)q * 32 + c4] =
            spgather_val4(q, c4, g_xw2, g_fused, b1, 0);
    }
}

// stage13: dense l1 GEMM + sparse l1 GEMM (merged, 96+96 blocks)
__global__ void k_stage13(const float* __restrict__ W0, const float* __restrict__ W1) {
    int b = blockIdx.x;
    if (b < 96) sgemm_block(g_tmpA, W0 + (size_t)DIM * DIM, nullptr, g_xw, TWO_N, DIM, DIM, DIM, DIM, b, 0);
    else        sgemm_block(g_tmpB, W1 + (size_t)DIM * DIM, nullptr, g_xw2, TWO_N, DIM, DIM, DIM, DIM, b - 96, 0);
}

// stage16: fused dense_combine l1 + spgather l1 -> emb (float4, 8 nodes/block)
__global__ void k_stage16(const float* __restrict__ b0, const float* __restrict__ b1) {
    int t = threadIdx.x;  // 256
    int q = blockIdx.x * 8 + (t >> 5);
    int c4 = t & 31;
    int i4 = q * 32 + c4;
    float4 dense = dense_combine_val4(i4, g_tmpA, b0, 1);
    float4 sp = spgather_val4(q, c4, g_xw2, g_tmpB, b1, 1);
    reinterpret_cast<float4*>(g_emb)[i4] =
        make_float4(dense.x + sp.x, dense.y + sp.y, dense.z + sp.z, dense.w + sp.w);
}

// ----------------------------- sm GEMM with fused softmax + entropy -------------------------------
__global__ void k_sm_gemm(const float* __restrict__ Wp, const float* __restrict__ bp) {
    __shared__ float As[2][16][33];
    __shared__ float Bs[2][16][128];
    int bm = blockIdx.x * 32;
    int tid = threadIdx.x;
    int tr = tid >> 5, tc = tid & 31;
    float acc[4][4];
    #pragma unroll
    for (int r = 0; r < 4; r++)
        #pragma unroll
        for (int c = 0; c < 4; c++) acc[r][c] = 0.f;

    #pragma unroll
    for (int j = 0; j < 2; j++) {
        int idx = tid + 256 * j;
        int m = idx >> 4, kk = idx & 15;
        As[0][kk][m] = g_emb[(size_t)(bm + m) * DIM + kk];
    }
    #pragma unroll
    for (int j = 0; j < 8; j++) {
        int idx = tid + 256 * j;
        int kk = idx >> 7, n = idx & 127;
        Bs[0][kk][n] = (n < CC) ? Wp[(size_t)kk * CC + n] : 0.f;
    }
    __syncthreads();
    int buf = 0;
    for (int k0 = 0; k0 < DIM; k0 += 16) {
        int nb = buf ^ 1;
        if (k0 + 16 < DIM) {
            #pragma unroll
            for (int j = 0; j < 2; j++) {
                int idx = tid + 256 * j;
                int m = idx >> 4, kk = idx & 15;
                As[nb][kk][m] = g_emb[(size_t)(bm + m) * DIM + k0 + 16 + kk];
            }
            #pragma unroll
            for (int j = 0; j < 8; j++) {
                int idx = tid + 256 * j;
                int kk = idx >> 7, n = idx & 127;
                Bs[nb][kk][n] = (n < CC) ? Wp[(size_t)(k0 + 16 + kk) * CC + n] : 0.f;
            }
        }
        #pragma unroll
        for (int kk = 0; kk < 16; kk++) {
            float a0 = As[buf][kk][tr * 4 + 0];
            float a1 = As[buf][kk][tr * 4 + 1];
            float a2 = As[buf][kk][tr * 4 + 2];
            float a3 = As[buf][kk][tr * 4 + 3];
            float4 b4 = *reinterpret_cast<const float4*>(&Bs[buf][kk][tc * 4]);
            acc[0][0] += a0 * b4.x; acc[0][1] += a0 * b4.y; acc[0][2] += a0 * b4.z; acc[0][3] += a0 * b4.w;
            acc[1][0] += a1 * b4.x; acc[1][1] += a1 * b4.y; acc[1][2] += a1 * b4.z; acc[1][3] += a1 * b4.w;
            acc[2][0] += a2 * b4.x; acc[2][1] += a2 * b4.y; acc[2][2] += a2 * b4.z; acc[2][3] += a2 * b4.w;
            acc[3][0] += a3 * b4.x; acc[3][1] += a3 * b4.y; acc[3][2] += a3 * b4.z; acc[3][3] += a3 * b4.w;
        }
        __syncthreads();
        buf = nb;
    }
    float entpart = 0.f;
    #pragma unroll
    for (int r = 0; r < 4; r++) {
        int row = bm + tr * 4 + r;
        float v[4];
        float mx = -1e30f;
        #pragma unroll
        for (int c = 0; c < 4; c++) {
            int n = tc * 4 + c;
            v[c] = (n < CC) ? (acc[r][c] + bp[n]) : -1e30f;
            mx = fmaxf(mx, v[c]);
        }
        #pragma unroll
        for (int o = 16; o > 0; o >>= 1) mx = fmaxf(mx, __shfl_xor_sync(0xffffffff, mx, o));
        float sm = 0.f;
        float ex[4];
        #pragma unroll
        for (int c = 0; c < 4; c++) {
            int n = tc * 4 + c;
            ex[c] = (n < CC) ? expf(v[c] - mx) : 0.f;
            sm += ex[c];
        }
        #pragma unroll
        for (int o = 16; o > 0; o >>= 1) sm += __shfl_xor_sync(0xffffffff, sm, o);
        float inv = 1.f / sm;
        #pragma unroll
        for (int c = 0; c < 4; c++) {
            int n = tc * 4 + c;
            if (n < CC) {
                float p = ex[c] * inv;
                g_sm[(size_t)row * CC + n] = p;
                entpart += -p * logf(p + 1e-15f);
            }
        }
    }
    #pragma unroll
    for (int o = 16; o > 0; o >>= 1) entpart += __shfl_xor_sync(0xffffffff, entpart, o);
    if (tc == 0) atomicAdd(&g_acc[2], entpart);
}

// ----------------------------- stage19: poolgram + cross/normA + qp2 GEMM -------------------------
// [0,192) poolgram | [192,6336) cross+normA per node | [6336,6432) qp2
__global__ void k_stage19(const float* __restrict__ m2bi) {
    extern __shared__ float dyn[];      // poolgram staging: S[32][104] + E[32][128]
    __shared__ float shred[256];
    int b = blockIdx.x;
    int t = threadIdx.x;  // 256
    if (b < 192) {            // poolgram
        float* S_s = dyn;
        float* E_s = dyn + 32 * 104;
        int i0 = b * 32;
        for (int idx = t; idx < 32 * CC; idx += 256) {
            int r = idx / CC, c = idx % CC;
            S_s[r * 104 + c] = g_sm[(size_t)(i0 + r) * CC + c];
        }
        for (int idx = t; idx < 32 * DIM; idx += 256) {
            int r = idx >> 7, d = idx & 127;
            E_s[r * 128 + d] = g_emb[(size_t)(i0 + r) * DIM + d];
        }
        __syncthreads();
        for (int o = t; o < CC * 32; o += 256) {
            int c = o >> 5, d4 = o & 31;
            float4 a = make_float4(0.f, 0.f, 0.f, 0.f);
            for (int r = 0; r < 32; r++) {
                float s = S_s[r * 104 + c];
                float4 e4 = *reinterpret_cast<const float4*>(&E_s[r * 128 + d4 * 4]);
                a.x += s * e4.x; a.y += s * e4.y; a.z += s * e4.z; a.w += s * e4.w;
            }
            atomicAdd(&g_pooled[(size_t)c * DIM + d4 * 4 + 0], a.x);
            atomicAdd(&g_pooled[(size_t)c * DIM + d4 * 4 + 1], a.y);
            atomicAdd(&g_pooled[(size_t)c * DIM + d4 * 4 + 2], a.z);
            atomicAdd(&g_pooled[(size_t)c * DIM + d4 * 4 + 3], a.w);
        }
        for (int o = t; o < CC * 25; o += 256) {
            int c1 = o / 25, c2g = o % 25;
            float4 a = make_float4(0.f, 0.f, 0.f, 0.f);
            for (int r = 0; r < 32; r++) {
                float s = S_s[r * 104 + c1];
                float4 s4 = *reinterpret_cast<const float4*>(&S_s[r * 104 + c2g * 4]);
                a.x += s * s4.x; a.y += s * s4.y; a.z += s * s4.z; a.w += s * s4.w;
            }
            atomicAdd(&g_G[c1 * CC + c2g * 4 + 0], a.x);
            atomicAdd(&g_G[c1 * CC + c2g * 4 + 1], a.y);
            atomicAdd(&g_G[c1 * CC + c2g * 4 + 2], a.z);
            atomicAdd(&g_G[c1 * CC + c2g * 4 + 3], a.w);
        }
    } else if (b < 6336) {    // per-node q: cross <A,SS^T> + duplicate-exact ||A||^2 (CSR, no Adense)
        int q = b - 192;
        int beg = g_csr_off[q], end = g_csr_off[q + 1];
        float acc = 0.f;
        if (t < CC) {
            float tsum = 0.f;
            for (int j = beg; j < end; j++)
                tsum += g_csr_w[j] * g_sm[(size_t)g_csr_src[j] * CC + t];
            acc = tsum * g_sm[(size_t)q * CC + t];
        }
        float s = blockReduceSum(acc, shred);
        if (t == 0 && s != 0.f) atomicAdd(&g_acc[1], s);
        // ||A||^2 within this destination's segment: group duplicate srcs exactly.
        // Thread owns edge j iff src[j] first occurs at j; then sums all duplicates' w and squares.
        float na = 0.f;
        for (int j = beg + t; j < end; j += 256) {
            int sj = g_csr_src[j];
            bool first = true;
            for (int j2 = beg; j2 < j; j2++)
                if (g_csr_src[j2] == sj) { first = false; break; }
            if (first) {
                float sumw = g_csr_w[j];
                for (int j2 = j + 1; j2 < end; j2++)
                    if (g_csr_src[j2] == sj) sumw += g_csr_w[j2];
                na += sumw * sumw;
            }
        }
        float sa = blockReduceSum(na, shred);
        if (t == 0 && sa != 0.f) atomicAdd(&g_acc[0], sa);
    } else {                  // qp2 GEMM (96 blocks)
        sgemm_block(g_emb, g_wt, m2bi, g_qp2, TWO_N, DIM, DIM, DIM, DIM, b - 6336, 0);
    }
}

// ----------------------------- stage20: kvproj only -----------------------------------------------
__global__ void k_stage20(const float* __restrict__ wi, const float* __restrict__ bi) {
    int b = blockIdx.x;
    int t = threadIdx.x;  // 256
    __shared__ float prow[DIM];
    int c = b >> 1, which = b & 1;
    if (t < 128) prow[t] = g_pooled[(size_t)c * DIM + t];
    __syncthreads();
    if (t >= 128) return;
    const float4* row4 = reinterpret_cast<const float4*>(wi + (size_t)(DIM + which * DIM + t) * DIM);
    float acc = bi[DIM + which * DIM + t];
    #pragma unroll
    for (int k = 0; k < 32; k++) {
        float4 r = row4[k];
        acc += r.x * prow[4 * k] + r.y * prow[4 * k + 1]
             + r.z * prow[4 * k + 2] + r.w * prow[4 * k + 3];
    }
    (which ? g_vp2 : g_kp2)[(size_t)c * DIM + t] = acc;
}

// ----------------------------- stage21: mha2 (2 queries/iter, 256 thr) + gramfin ------------------
#define K_LD 129
__global__ void k_stage21(const float* __restrict__ wo, const float* __restrict__ bo,
                          float* __restrict__ out_skill, float* __restrict__ out_loss) {
    extern __shared__ float kp_s[];     // [CC][K_LD]
    int t = threadIdx.x;  // 256
    if (blockIdx.x == 384) {            // gramfin
        __shared__ float sh[256];
        float acc = 0.f;
        for (int i = t; i < CC * CC; i += 256) { float g = g_G[i]; acc += g * g; }
        float s = blockReduceSum(acc, sh);
        if (t == 0) {
            float n2 = g_acc[0] - 2.f * g_acc[1] + s;
            float link = sqrtf(fmaxf(n2, 0.f)) / ((float)TWO_N * (float)TWO_N);
            out_loss[0] = link + g_acc[2] / (float)TWO_N;
        }
        return;
    }
    __shared__ float qrow[2][DIM];
    __shared__ float lg[2][HH][CC];
    __shared__ float o_s[2][DIM];
    int g = t >> 7;            // query group 0/1
    int tg = t & 127;
    int w = tg >> 5, lane = tg & 31;
    for (int i = t; i < CC * DIM; i += 256) {
        int j = i >> 7, d = i & 127;
        kp_s[j * K_LD + d] = g_kp2[i];
    }
    __syncthreads();
    int n0 = blockIdx.x * 16;
    for (int q = 0; q < 16; q += 2) {
        int n = n0 + q + g;
        qrow[g][tg] = g_qp2[(size_t)n * DIM + tg];
        __syncthreads();
        for (int pos = tg; pos < HH * CC; pos += 128) {
            int h = pos / CC, j = pos % CC;
            float acc = 0.f;
            #pragma unroll 8
            for (int d = 0; d < HD; d++)
                acc += qrow[g][h * HD + d] * kp_s[j * K_LD + h * HD + d];
            lg[g][h][j] = acc * INV_SQRT_HD;
        }
        __syncthreads();
        {
            float mx = -1e30f;
            for (int j = lane; j < CC; j += 32) mx = fmaxf(mx, lg[g][w][j]);
            #pragma unroll
            for (int o = 16; o > 0; o >>= 1) mx = fmaxf(mx, __shfl_xor_sync(0xffffffff, mx, o));
            float sm = 0.f;
            for (int j = lane; j < CC; j += 32) { float e = expf(lg[g][w][j] - mx); lg[g][w][j] = e; sm += e; }
            #pragma unroll
            for (int o = 16; o > 0; o >>= 1) sm += __shfl_xor_sync(0xffffffff, sm, o);
            float inv = 1.f / sm;
            for (int j = lane; j < CC; j += 32) lg[g][w][j] *= inv;
        }
        __syncthreads();
        {
            float acc = 0.f;
            for (int j = 0; j < CC; j++) acc += lg[g][w][j] * g_vp2[(size_t)j * DIM + tg];
            o_s[g][tg] = acc;
        }
        __syncthreads();
        {
            const float4* row4 = reinterpret_cast<const float4*>(wo + (size_t)tg * DIM);
            float acc = bo[tg];
            #pragma unroll
            for (int k = 0; k < 32; k++) {
                float4 r = row4[k];
                acc += r.x * o_s[g][4 * k] + r.y * o_s[g][4 * k + 1]
                     + r.z * o_s[g][4 * k + 2] + r.w * o_s[g][4 * k + 3];
            }
            out_skill[(size_t)n * DIM + tg] = 2.f * g_emb[(size_t)n * DIM + tg] + acc;
        }
        __syncthreads();
    }
}

// ----------------------------- host launch -----------------------------
extern "C" void kernel_launch(void* const* d_in, const int* in_sizes, int n_in,
                              void* d_out, int out_size) {
    const float* demand = (const float*)d_in[0];
    const float* supply = (const float*)d_in[1];
    const float* skill  = (const float*)d_in[2];
    const int*   eidx   = (const int*)d_in[3];
    const float* eattr  = (const float*)d_in[4];
    const float* w_fuse = (const float*)d_in[5];
    const float* b_fuse = (const float*)d_in[6];
    const float* m1wi   = (const float*)d_in[7];
    const float* m1bi   = (const float*)d_in[8];
    const float* m1wo   = (const float*)d_in[9];
    const float* m1bo   = (const float*)d_in[10];
    const float* m2wi   = (const float*)d_in[11];
    const float* m2bi   = (const float*)d_in[12];
    const float* m2wo   = (const float*)d_in[13];
    const float* m2bo   = (const float*)d_in[14];
    const float* sender = (const float*)d_in[15];
    const float* recv   = (const float*)d_in[16];
    const float* W0     = (const float*)d_in[17];
    const float* b0     = (const float*)d_in[18];
    const float* W1     = (const float*)d_in[19];
    const float* b1     = (const float*)d_in[20];
    const float* Wp     = (const float*)d_in[21];
    const float* bp     = (const float*)d_in[22];
    float* out = (float*)d_out;
    const int* src = eidx;
    const int* dst = eidx + EE;

    cudaFuncSetAttribute(k_stage19, cudaFuncAttributeMaxDynamicSharedMemorySize,
                         (32 * 104 + 32 * 128) * (int)sizeof(float) + 1024);
    cudaFuncSetAttribute(k_stage21, cudaFuncAttributeMaxDynamicSharedMemorySize,
                         CC * K_LD * (int)sizeof(float) + 2048);

    float *p_cq, *p_wbig, *p_fb, *p_fused;
    cudaGetSymbolAddress((void**)&p_cq, g_cq);
    cudaGetSymbolAddress((void**)&p_wbig, g_wbig);
    cudaGetSymbolAddress((void**)&p_fb, g_fb);
    cudaGetSymbolAddress((void**)&p_fused, g_fused);

    k_init<<<64, 256>>>(sender, recv);
    k_stage1<<<3443, 256>>>(m1wi, m1wo, m1bo, m1bi, m2wi, demand, supply, dst, eattr,
                            out + OUT_PRED);
    k_stage2<<<769, 1024>>>(skill, out + OUT_CAT);
    k_stage3<<<457, 256>>>(w_fuse, b_fuse);
    k_attn1<<<TWO_N + 1536, 128>>>(demand, supply, src, dst, eattr);
    k_sgemm<<<dim3(1, 96), 256>>>(p_cq, p_wbig, p_fb, p_fused, TWO_N, DIM, 640, DIM);

    k_stage8<<<3264, 256>>>(sender, recv, W0, W1);
    k_scores<<<1184, 256>>>();
    k_predg_general<<<TWO_N, 256>>>(out + OUT_PRED);
    k_dense_agg<<<TWO_N / 32, 256>>>();
    k_stage12<<<1536, 256>>>(b0, b1);
    k_stage13<<<192, 256>>>(W0, W1);
    k_dense_agg<<<TWO_N / 32, 256>>>();
    k_stage16<<<768, 256>>>(b0, b1);

    k_sm_gemm<<<192, 256>>>(Wp, bp);
    k_stage19<<<6432, 256, (32 * 104 + 32 * 128) * sizeof(float)>>>(m2bi);
    k_stage20<<<200, 256>>>(m2wi, m2bi);
    k_stage21<<<385, 256, CC * K_LD * sizeof(float) + 2048>>>(m2wo, m2bo, out + OUT_SKILL, out + OUT_LOSS);
}

// round 17
// speedup vs baseline: 1.3066x; 1.3066x over previous
#include <cuda_runtime.h>
#include <math.h>

#define NN      3072
#define TWO_N   6144
#define DIM     128
#define SEQ     16
#define EE      196608
#define CC      100
#define HH      4
#define HD      32
#define INV_SQRT_HD 0.17677669529663687f
#define DELTA_T 0.1f
#define PRESERVE 0.1f

#define OUT_CAT   0
#define OUT_SKILL (TWO_N * DIM)
#define OUT_PRED  (2 * TWO_N * DIM)
#define OUT_LOSS  (2 * TWO_N * DIM + TWO_N * TWO_N)

// ----------------------------- device scratch -----------------------------
__device__ float g_dsum[DIM];
__device__ float g_ssum[DIM];
__device__ float g_fused[(size_t)TWO_N * DIM];
__device__ float g_s1[(size_t)TWO_N * DIM];
__device__ float g_s2[(size_t)TWO_N * DIM];
__device__ float g_scores[(size_t)TWO_N * TWO_N];   // general path only
__device__ float g_Adense[(size_t)TWO_N * TWO_N];   // zero between launches (exch trick)
__device__ float g_deg[TWO_N];
__device__ float g_degsp[TWO_N];
__device__ float g_xw[(size_t)TWO_N * DIM];     // dense chain
__device__ float g_xw2[(size_t)TWO_N * DIM];    // sparse chain
__device__ float g_agg[(size_t)TWO_N * DIM];
__device__ float g_tmpA[(size_t)TWO_N * DIM];
__device__ float g_tmpB[(size_t)TWO_N * DIM];
__device__ float g_emb[(size_t)TWO_N * DIM];
__device__ float g_sm[(size_t)TWO_N * CC];
__device__ float g_pooled[CC * DIM];
__device__ float g_G[CC * CC];
__device__ float g_kp2[CC * DIM];
__device__ float g_vp2[CC * DIM];
__device__ float g_qp2[(size_t)TWO_N * DIM];
__device__ float g_wt[DIM * DIM];
__device__ float g_acc[8];   // [0]=||A||^2 [1]=<A,SS^T> [2]=ent_sum
__device__ int   g_flag;

// MHA1 chain buffers
__device__ float g_qv[(size_t)TWO_N * DIM];
__device__ float g_U[(size_t)TWO_N * 4 * DIM];         // [2N, 512]
__device__ float g_cq[(size_t)TWO_N * 640];            // [skill(128) | c(512)] per row
__device__ float g_Zcat[4 * DIM * DIM];                // [512, 128]
__device__ float g_zb[DIM];
__device__ float g_Wcomb[DIM * 4 * DIM];               // [128, 512]
__device__ float g_Ub[4 * DIM];                        // [512]
__device__ float g_vqb[DIM * HH];                      // [128][4]
__device__ float g_cb[HH];
__device__ float g_wbig[640 * DIM];                    // [Wf_top(128); Zf(512)] x 128
__device__ float g_fb[DIM];

// CSR for sparse GCN (+ raw weights for link loss)
__device__ int   g_csr_cnt[TWO_N];
__device__ int   g_csr_off[TWO_N + 1];
__device__ int   g_csr_src[EE];
__device__ float g_csr_coef[EE];
__device__ float g_csr_w[EE];

// ----------------------------- helpers -----------------------------
__device__ __forceinline__ float blockReduceSum(float v, float* sh) {
    int t = threadIdx.x;
    sh[t] = v; __syncthreads();
    for (int s = blockDim.x >> 1; s > 0; s >>= 1) {
        if (t < s) sh[t] += sh[t + s];
        __syncthreads();
    }
    float r = sh[0]; __syncthreads();
    return r;
}
__device__ __forceinline__ float blockReduceMax(float v, float* sh) {
    int t = threadIdx.x;
    sh[t] = v; __syncthreads();
    for (int s = blockDim.x >> 1; s > 0; s >>= 1) {
        if (t < s) sh[t] = fmaxf(sh[t], sh[t + s]);
        __syncthreads();
    }
    float r = sh[0]; __syncthreads();
    return r;
}

// ---------------- SGEMM device block-function: 64x128 tile, 8x4/thread, double-buffered ----------
__device__ void sgemm_block(const float* __restrict__ A, const float* __restrict__ B,
                            const float* __restrict__ bias, float* __restrict__ Cmat,
                            int M, int Nn, int K, int lda, int ldc, int bmi, int bni) {
    __shared__ float As[2][16][65];
    __shared__ float Bs[2][16][128];
    int bm = bmi * 64;
    int bn = bni * 128;
    int tid = threadIdx.x;
    int tr = tid >> 5, tc = tid & 31;
    float acc[8][4];
    #pragma unroll
    for (int r = 0; r < 8; r++)
        #pragma unroll
        for (int c = 0; c < 4; c++) acc[r][c] = 0.f;

    #pragma unroll
    for (int j = 0; j < 4; j++) {
        int idx = tid + 256 * j;
        int m = idx >> 4, kk = idx & 15;
        int row = bm + m; if (row >= M) row = M - 1;
        As[0][kk][m] = A[(size_t)row * lda + kk];
    }
    #pragma unroll
    for (int j = 0; j < 8; j++) {
        int idx = tid + 256 * j;
        int kk = idx >> 7, n = idx & 127;
        Bs[0][kk][n] = (bn + n < Nn) ? B[(size_t)kk * Nn + bn + n] : 0.f;
    }
    __syncthreads();

    int buf = 0;
    for (int k0 = 0; k0 < K; k0 += 16) {
        int nb = buf ^ 1;
        if (k0 + 16 < K) {
            #pragma unroll
            for (int j = 0; j < 4; j++) {
                int idx = tid + 256 * j;
                int m = idx >> 4, kk = idx & 15;
                int row = bm + m; if (row >= M) row = M - 1;
                As[nb][kk][m] = A[(size_t)row * lda + k0 + 16 + kk];
            }
            #pragma unroll
            for (int j = 0; j < 8; j++) {
                int idx = tid + 256 * j;
                int kk = idx >> 7, n = idx & 127;
                Bs[nb][kk][n] = (bn + n < Nn) ? B[(size_t)(k0 + 16 + kk) * Nn + bn + n] : 0.f;
            }
        }
        #pragma unroll
        for (int kk = 0; kk < 16; kk++) {
            float4 b4 = *reinterpret_cast<const float4*>(&Bs[buf][kk][tc * 4]);
            #pragma unroll
            for (int r = 0; r < 8; r++) {
                float a = As[buf][kk][tr * 8 + r];
                acc[r][0] += a * b4.x; acc[r][1] += a * b4.y;
                acc[r][2] += a * b4.z; acc[r][3] += a * b4.w;
            }
        }
        __syncthreads();
        buf = nb;
    }
    #pragma unroll
    for (int r = 0; r < 8; r++) {
        int m = bm + tr * 8 + r;
        if (m >= M) continue;
        #pragma unroll
        for (int c = 0; c < 4; c++) {
            int n = bn + tc * 4 + c;
            if (n < Nn) {
                float v = acc[r][c];
                if (bias) v += bias[n];
                Cmat[(size_t)m * ldc + n] = v;
            }
        }
    }
}

__global__ void k_sgemm(const float* __restrict__ A, const float* __restrict__ B,
                        const float* __restrict__ bias, float* __restrict__ Cmat,
                        int M, int Nn, int K, int ldc) {
    sgemm_block(A, B, bias, Cmat, M, Nn, K, K, ldc, blockIdx.y, blockIdx.x);
}

// ----------------------------- init -----------------------------
__global__ void k_init(const float* __restrict__ sender, const float* __restrict__ receiver) {
    int i = blockIdx.x * blockDim.x + threadIdx.x;
    if (i < TWO_N) { g_deg[i] = 1.0f; g_degsp[i] = 1.0f; g_csr_cnt[i] = 0; }
    if (i < CC * DIM) g_pooled[i] = 0.f;
    if (i < CC * CC) g_G[i] = 0.f;
    if (i < 2 * DIM) (i < DIM ? g_dsum : g_ssum)[i & 127] = 0.f;
    if (i < 8) g_acc[i] = 0.f;
    if (i == 0) g_flag = (sender[0] == receiver[0]) ? 1 : 0;
}

// ----------------------------- stage1: prep + seqsum + edge1 + predg_zero -------------------------
__global__ void k_stage1(const float* __restrict__ m1wi, const float* __restrict__ m1wo,
                         const float* __restrict__ m1bo, const float* __restrict__ m1bi,
                         const float* __restrict__ m2wi,
                         const float* __restrict__ demand, const float* __restrict__ supply,
                         const int* __restrict__ dst, const float* __restrict__ w,
                         float* __restrict__ out_pred) {
    int b = blockIdx.x;
    int t = threadIdx.x;  // 256
    if (b < 256) {                        // Zcat
        int i = b * 256 + t;
        int row = i >> 7, tt = i & 127;
        int h = row >> 7, d = row & 127;
        const float* wv = m1wi + (size_t)2 * DIM * DIM;
        float acc = 0.f;
        #pragma unroll 8
        for (int j = 0; j < 32; j++)
            acc += m1wo[(size_t)tt * DIM + h * 32 + j] * wv[(size_t)(h * 32 + j) * DIM + d];
        g_Zcat[(size_t)row * DIM + tt] = acc;
    } else if (b == 256) {                // zb
        if (t < DIM) {
            const float* bv = m1bi + 2 * DIM;
            float acc = m1bo[t];
            #pragma unroll 8
            for (int k = 0; k < DIM; k++) acc += m1wo[(size_t)t * DIM + k] * bv[k];
            g_zb[t] = acc;
        }
    } else if (b < 321) {                 // m2wi transpose (64)
        int i = (b - 257) * 256 + t;
        int n = i >> 7, k = i & 127;
        g_wt[(size_t)k * DIM + n] = m2wi[(size_t)n * DIM + k];
    } else if (b < 369) {                 // seqsum (48)
        if (t < DIM) {
            int sb = b - 321;
            int tensor = sb / 24, chunk = sb % 24;
            const float* base = tensor ? supply : demand;
            float acc = 0.f;
            int n0 = chunk * 128;
            for (int n = n0; n < n0 + 128; n++)
                acc += base[(size_t)n * SEQ * DIM + (size_t)(SEQ - 1) * DIM + t];
            atomicAdd(&(tensor ? g_ssum : g_dsum)[t], acc);
        }
    } else if (b < 1137) {                // edge1 (768)
        int e = (b - 369) * 256 + t;
        if (e < EE) {
            int q = dst[e];
            atomicAdd(&g_degsp[q], w[e]);
            atomicAdd(&g_csr_cnt[q], 1);
        }
    } else if (b < 1393) {                // Wcomb (256): [128,512]
        int i = (b - 1137) * 256 + t;
        int k = i >> 9, col = i & 511;
        int h = col >> 7, d = col & 127;
        const float* wk = m1wi + (size_t)DIM * DIM;
        float acc = 0.f;
        #pragma unroll 8
        for (int j = 0; j < 32; j++)
            acc += m1wi[(size_t)(h * 32 + j) * DIM + k] * wk[(size_t)(h * 32 + j) * DIM + d];
        g_Wcomb[(size_t)k * 512 + col] = acc;
    } else if (b == 1393) {               // vqb [128][4]
        for (int i = t; i < DIM * HH; i += 256) {
            int k = i >> 2, h = i & 3;
            const float* bk = m1bi + DIM;
            float acc = 0.f;
            #pragma unroll 8
            for (int j = 0; j < 32; j++)
                acc += m1wi[(size_t)(h * 32 + j) * DIM + k] * bk[h * 32 + j];
            g_vqb[i] = acc;
        }
    } else if (b == 1394) {               // Ub [512] + cb[4]
        const float* wk = m1wi + (size_t)DIM * DIM;
        const float* bk = m1bi + DIM;
        for (int col = t; col < 512; col += 256) {
            int h = col >> 7, d = col & 127;
            float acc = 0.f;
            #pragma unroll 8
            for (int j = 0; j < 32; j++)
                acc += m1bi[h * 32 + j] * wk[(size_t)(h * 32 + j) * DIM + d];
            g_Ub[col] = acc;
        }
        if (t < HH) {
            float acc = 0.f;
            for (int j = 0; j < 32; j++) acc += m1bi[t * 32 + j] * bk[t * 32 + j];
            g_cb[t] = acc;
        }
    } else {                              // predg zero-fill (flag path) (2048)
        if (!g_flag) return;
        float4 z = make_float4(0.f, 0.f, 0.f, 0.f);
        float4* o = reinterpret_cast<float4*>(out_pred);
        size_t total = (size_t)TWO_N * TWO_N / 4;
        for (size_t j = (size_t)(b - 1395) * 256 + t; j < total; j += (size_t)2048 * 256)
            o[j] = z;
    }
}

// ----------------------------- stage2: scan (b0) + qv (merged, 1024 threads) ----------------------
__global__ void k_stage2(const float* __restrict__ skill, float* __restrict__ out_cat) {
    int b = blockIdx.x;
    int t = threadIdx.x;  // 1024
    if (b == 0) {         // scan
        __shared__ int sh[1024];
        int base = t * 6;
        int loc[6];
        int s = 0;
        #pragma unroll
        for (int k = 0; k < 6; k++) { loc[k] = s; s += g_csr_cnt[base + k]; }
        sh[t] = s;
        __syncthreads();
        for (int off = 1; off < 1024; off <<= 1) {
            int add = (t >= off) ? sh[t - off] : 0;
            __syncthreads();
            sh[t] += add;
            __syncthreads();
        }
        int excl = sh[t] - s;
        #pragma unroll
        for (int k = 0; k < 6; k++) {
            int o = excl + loc[k];
            g_csr_off[base + k] = o;
            g_csr_cnt[base + k] = o;
        }
        if (t == 1023) g_csr_off[TWO_N] = sh[1023];
    } else {              // qv + cq skill half + out_cat
        int i = (b - 1) * 1024 + t;
        int bb = i >> 7, tt = i & 127;
        bool dem = bb < NN;
        int idx = dem ? bb : bb - NN;
        float sv = skill[(size_t)idx * DIM + tt];
        g_qv[i] = sv + (dem ? g_dsum : g_ssum)[tt];
        g_cq[(size_t)bb * 640 + tt] = sv;
        out_cat[i] = sv;
    }
}

// ----------------------------- stage3: Wtop + Zf GEMM + fb + U GEMM -------------------------------
__global__ void k_stage3(const float* __restrict__ w_fuse, const float* __restrict__ b_fuse) {
    int b = blockIdx.x;
    int t = threadIdx.x;  // 256
    if (b < 64) {             // Wtop copy
        int i = b * 256 + t;
        g_wbig[i] = w_fuse[i];
    } else if (b < 72) {      // Zf = Zcat @ Wf_bot -> wbig rows 128..639
        sgemm_block(g_Zcat, w_fuse + (size_t)DIM * DIM, nullptr, g_wbig + (size_t)DIM * DIM,
                    512, DIM, DIM, DIM, DIM, b - 64, 0);
    } else if (b == 72) {     // fb
        if (t < DIM) {
            float acc = b_fuse[t];
            #pragma unroll 8
            for (int k = 0; k < DIM; k++) acc += g_zb[k] * w_fuse[(size_t)(DIM + k) * DIM + t];
            g_fb[t] = acc;
        }
    } else {                  // U = qv @ Wcomb + Ub (384 blocks)
        int idx = b - 73;
        sgemm_block(g_qv, g_Wcomb, g_Ub, g_U, TWO_N, 4 * DIM, DIM, DIM, 4 * DIM,
                    idx % 96, idx / 96);
    }
}

// ----------------------------- attn1 + fillcsr (merged, 128 threads) ------------------------------
__global__ void k_attn1(const float* __restrict__ demand, const float* __restrict__ supply,
                        const int* __restrict__ src, const int* __restrict__ dst,
                        const float* __restrict__ w) {
    int b = blockIdx.x;
    int t = threadIdx.x;  // 128
    if (b >= TWO_N) {     // fillcsr
        int e = (b - TWO_N) * 128 + t;
        if (e < EE) {
            int s = src[e], q = dst[e];
            float we = w[e];
            int pos = atomicAdd(&g_csr_cnt[q], 1);
            g_csr_src[pos] = s;
            g_csr_coef[pos] = rsqrtf(g_degsp[s]) * rsqrtf(g_degsp[q]) * we;
            g_csr_w[pos] = we;
        }
        return;
    }
    int wd = t >> 5, lane = t & 31;
    bool dem = b < NN;
    int idx = dem ? b : b - NN;
    const float* seq = (dem ? demand : supply) + (size_t)idx * SEQ * DIM;

    __shared__ float sh_seq[SEQ][DIM + 1];
    __shared__ float sh_U[HH][DIM];
    __shared__ float sh_p[HH][SEQ];

    for (int i = t; i < SEQ * DIM; i += 128) sh_seq[i >> 7][i & 127] = seq[i];
    for (int i = t; i < HH * DIM; i += 128) sh_U[i >> 7][i & 127] = g_U[(size_t)b * 512 + i];
    __syncthreads();

    float qb = 0.f;
    #pragma unroll
    for (int m = 0; m < 4; m++) {
        int k = lane + 32 * m;
        qb += g_qv[(size_t)b * DIM + k] * g_vqb[k * HH + wd];
    }
    #pragma unroll
    for (int o = 16; o > 0; o >>= 1) qb += __shfl_xor_sync(0xffffffff, qb, o);
    qb += g_cb[wd];

    float myl = -1e30f;
    if (lane < SEQ) {
        float acc = 0.f;
        #pragma unroll 16
        for (int d = 0; d < DIM; d++) acc += sh_U[wd][d] * sh_seq[lane][d];
        myl = (acc + qb) * INV_SQRT_HD;
    }
    float mx = myl;
    #pragma unroll
    for (int o = 8; o > 0; o >>= 1) mx = fmaxf(mx, __shfl_xor_sync(0xffffffff, mx, o));
    float e = (lane < SEQ) ? expf(myl - mx) : 0.f;
    float sm = e;
    #pragma unroll
    for (int o = 8; o > 0; o >>= 1) sm += __shfl_xor_sync(0xffffffff, sm, o);
    if (lane < SEQ) sh_p[wd][lane] = e / sm;
    __syncthreads();

    #pragma unroll
    for (int k = 0; k < 4; k++) {
        int d = lane + 32 * k;
        float acc = 0.f;
        #pragma unroll
        for (int s = 0; s < SEQ; s++) acc += sh_p[wd][s] * sh_seq[s][d];
        g_cq[(size_t)b * 640 + 128 + wd * DIM + d] = acc;
    }
}

// ----------------------------- stage8: dense-l0 GEMM + sparse-l0 GEMM + tanhprep (grid-stride) ----
__global__ void k_stage8(const float* __restrict__ sender, const float* __restrict__ receiver,
                         const float* __restrict__ W0, const float* __restrict__ W1) {
    int b = blockIdx.x;
    if (b < 96) {
        sgemm_block(g_fused, W0, nullptr, g_xw, TWO_N, DIM, DIM, DIM, DIM, b, 0);
    } else if (b < 192) {
        sgemm_block(g_fused, W1, nullptr, g_xw2, TWO_N, DIM, DIM, DIM, DIM, b - 96, 0);
    } else {
        if (g_flag) return;
        float sv = sender[0], rv = receiver[0];
        for (int i = (b - 192) * 256 + threadIdx.x; i < TWO_N * DIM; i += 256 * 256) {
            float f = g_fused[i];
            g_s1[i] = tanhf(sv * f);
            g_s2[i] = tanhf(rv * f);
        }
    }
}

// ----------------------------- scores (general path; grid-stride) -----------------------------
__global__ void k_scores() {
    if (g_flag) return;
    __shared__ float A1[16][DIM], A2[16][DIM], B1[16][DIM], B2[16][DIM];
    int t = threadIdx.x;  // 256
    const int TILES = TWO_N / 16;
    for (int tile = blockIdx.x; tile < TILES * TILES; tile += gridDim.x) {
        int i0 = (tile / TILES) * 16, j0 = (tile % TILES) * 16;
        __syncthreads();
        for (int j = 0; j < 8; j++) {
            int idx = t + 256 * j;
            int r = idx >> 7, c = idx & 127;
            A1[r][c] = g_s1[(size_t)(i0 + r) * DIM + c];
            A2[r][c] = g_s2[(size_t)(i0 + r) * DIM + c];
            B1[r][c] = g_s1[(size_t)(j0 + r) * DIM + c];
            B2[r][c] = g_s2[(size_t)(j0 + r) * DIM + c];
        }
        __syncthreads();
        int ti = t >> 4, tj = t & 15;
        float acc = 0.f;
        for (int k = 0; k < DIM; k++)
            acc += A1[ti][k] * B2[tj][k] - A2[ti][k] * B1[tj][k];
        g_scores[(size_t)(i0 + ti) * TWO_N + j0 + tj] = acc;
    }
}

// ----------------------------- predg general (softmax+threshold+deg) ------------------------------
__global__ void k_predg_general(float* __restrict__ out_pred) {
    if (g_flag) return;
    int row = blockIdx.x;
    int t = threadIdx.x;  // 256
    __shared__ float sh[256];
    float* sr = g_scores + (size_t)row * TWO_N;
    float mx = 0.f;
    for (int i = t; i < TWO_N; i += 256) mx = fmaxf(mx, fmaxf(sr[i], 0.f));
    mx = blockReduceMax(mx, sh);
    float sum = 0.f;
    for (int i = t; i < TWO_N; i += 256) sum += expf(fmaxf(sr[i], 0.f) - mx);
    sum = blockReduceSum(sum, sh);
    float inv = 1.f / sum;
    for (int i = t; i < TWO_N; i += 256) {
        float p = expf(fmaxf(sr[i], 0.f) - mx) * inv;
        float pr = fmaxf(p - DELTA_T, 0.f);
        sr[i] = pr;
        out_pred[(size_t)row * TWO_N + i] = pr;
        if (pr != 0.f) atomicAdd(&g_deg[i], pr);
    }
}

// ----------------------------- dense agg (general path) -----------------------------
__global__ void k_dense_agg() {
    if (g_flag) return;
    int i0 = blockIdx.x * 32;
    int t = threadIdx.x;  // 256
    __shared__ float pcol[32];
    __shared__ float xrow[DIM];
    int dbase = t & 127, half = t >> 7;
    float acc[16];
    #pragma unroll
    for (int r = 0; r < 16; r++) acc[r] = 0.f;
    for (int j = 0; j < TWO_N; j++) {
        if (t < 32) pcol[t] = g_scores[(size_t)j * TWO_N + i0 + t];
        else if (t >= 128 && t < 256) {
            float sj = rsqrtf(g_deg[j]);
            xrow[t - 128] = sj * g_xw[(size_t)j * DIM + (t - 128)];
        }
        __syncthreads();
        #pragma unroll
        for (int r = 0; r < 16; r++) acc[r] += pcol[half + 2 * r] * xrow[dbase];
        __syncthreads();
    }
    #pragma unroll
    for (int r = 0; r < 16; r++) {
        int i = i0 + half + 2 * r;
        float di = rsqrtf(g_deg[i]);
        g_agg[(size_t)i * DIM + dbase] = acc[r] + di * g_xw[(size_t)i * DIM + dbase];
    }
}

// ---------------- device bodies: float4 dense combine / sparse gather ----------------
__device__ __forceinline__ float4 dense_combine_val4(int i4, const float* __restrict__ prev,
                                                     const float* __restrict__ b0, int layer) {
    int i = i4 * 4;
    int row = i >> 7, cb = i & 127;
    float di = rsqrtf(g_deg[row]);
    const float4* xw4 = reinterpret_cast<const float4*>(g_xw);
    const float4* agg4 = reinterpret_cast<const float4*>(g_agg);
    float4 v;
    if (g_flag) {
        float s = di * di;
        float4 x = xw4[i4];
        v = make_float4(s * x.x, s * x.y, s * x.z, s * x.w);
    } else {
        float4 a = agg4[i4];
        v = make_float4(di * a.x, di * a.y, di * a.z, di * a.w);
    }
    const float4* b4p = reinterpret_cast<const float4*>(b0 + layer * DIM + cb);
    float4 bb = *b4p;
    const float4* p4 = reinterpret_cast<const float4*>(prev);
    float4 pv = p4[i4];
    float4 r;
    r.x = (1.f - PRESERVE) * (v.x + bb.x) + PRESERVE * pv.x;
    r.y = (1.f - PRESERVE) * (v.y + bb.y) + PRESERVE * pv.y;
    r.z = (1.f - PRESERVE) * (v.z + bb.z) + PRESERVE * pv.z;
    r.w = (1.f - PRESERVE) * (v.w + bb.w) + PRESERVE * pv.w;
    return r;
}
__device__ __forceinline__ float4 spgather_val4(int q, int c4, const float* __restrict__ xw,
                                                const float* __restrict__ prev,
                                                const float* __restrict__ b1, int layer) {
    const float4* xw4 = reinterpret_cast<const float4*>(xw);
    float dv = rsqrtf(g_degsp[q]);
    float s0c = dv * dv;
    float4 x0 = xw4[(size_t)q * 32 + c4];
    float4 acc = make_float4(s0c * x0.x, s0c * x0.y, s0c * x0.z, s0c * x0.w);
    int beg = g_csr_off[q], end = g_csr_off[q + 1];
    for (int j = beg; j < end; j++) {
        float cf = g_csr_coef[j];
        int s = g_csr_src[j];
        float4 x = xw4[(size_t)s * 32 + c4];
        acc.x += cf * x.x; acc.y += cf * x.y; acc.z += cf * x.z; acc.w += cf * x.w;
    }
    const float4* b4p = reinterpret_cast<const float4*>(b1 + layer * DIM + c4 * 4);
    float4 bb = *b4p;
    const float4* p4 = reinterpret_cast<const float4*>(prev);
    float4 pv = p4[(size_t)q * 32 + c4];
    float4 r;
    r.x = (1.f - PRESERVE) * (acc.x + bb.x) + PRESERVE * pv.x;
    r.y = (1.f - PRESERVE) * (acc.y + bb.y) + PRESERVE * pv.y;
    r.z = (1.f - PRESERVE) * (acc.z + bb.z) + PRESERVE * pv.z;
    r.w = (1.f - PRESERVE) * (acc.w + bb.w) + PRESERVE * pv.w;
    return r;
}

// stage12: dense_combine l0 (float4) + spgather l0 (float4, 8 nodes/block)
__global__ void k_stage12(const float* __restrict__ b0, const float* __restrict__ b1) {
    int b = blockIdx.x;
    int t = threadIdx.x;  // 256
    if (b < 768) {
        int i4 = b * 256 + t;
        reinterpret_cast<float4*>(g_tmpA)[i4] = dense_combine_val4(i4, g_fused, b0, 0);
    } else {
        int q = (b - 768) * 8 + (t >> 5);
        int c4 = t & 31;
        reinterpret_cast<float4*>(g_tmpB)[(size_t)q * 32 + c4] =
            spgather_val4(q, c4, g_xw2, g_fused, b1, 0);
    }
}

// stage13: dense l1 GEMM + sparse l1 GEMM (merged, 96+96 blocks)
__global__ void k_stage13(const float* __restrict__ W0, const float* __restrict__ W1) {
    int b = blockIdx.x;
    if (b < 96) sgemm_block(g_tmpA, W0 + (size_t)DIM * DIM, nullptr, g_xw, TWO_N, DIM, DIM, DIM, DIM, b, 0);
    else        sgemm_block(g_tmpB, W1 + (size_t)DIM * DIM, nullptr, g_xw2, TWO_N, DIM, DIM, DIM, DIM, b - 96, 0);
}

// stage16: fused dense_combine l1 + spgather l1 -> emb (float4, 8 nodes/block)
__global__ void k_stage16(const float* __restrict__ b0, const float* __restrict__ b1) {
    int t = threadIdx.x;  // 256
    int q = blockIdx.x * 8 + (t >> 5);
    int c4 = t & 31;
    int i4 = q * 32 + c4;
    float4 dense = dense_combine_val4(i4, g_tmpA, b0, 1);
    float4 sp = spgather_val4(q, c4, g_xw2, g_tmpB, b1, 1);
    reinterpret_cast<float4*>(g_emb)[i4] =
        make_float4(dense.x + sp.x, dense.y + sp.y, dense.z + sp.z, dense.w + sp.w);
}

// ----------------------------- sm GEMM with fused softmax + entropy -------------------------------
__global__ void k_sm_gemm(const float* __restrict__ Wp, const float* __restrict__ bp) {
    __shared__ float As[2][16][33];
    __shared__ float Bs[2][16][128];
    int bm = blockIdx.x * 32;
    int tid = threadIdx.x;
    int tr = tid >> 5, tc = tid & 31;
    float acc[4][4];
    #pragma unroll
    for (int r = 0; r < 4; r++)
        #pragma unroll
        for (int c = 0; c < 4; c++) acc[r][c] = 0.f;

    #pragma unroll
    for (int j = 0; j < 2; j++) {
        int idx = tid + 256 * j;
        int m = idx >> 4, kk = idx & 15;
        As[0][kk][m] = g_emb[(size_t)(bm + m) * DIM + kk];
    }
    #pragma unroll
    for (int j = 0; j < 8; j++) {
        int idx = tid + 256 * j;
        int kk = idx >> 7, n = idx & 127;
        Bs[0][kk][n] = (n < CC) ? Wp[(size_t)kk * CC + n] : 0.f;
    }
    __syncthreads();
    int buf = 0;
    for (int k0 = 0; k0 < DIM; k0 += 16) {
        int nb = buf ^ 1;
        if (k0 + 16 < DIM) {
            #pragma unroll
            for (int j = 0; j < 2; j++) {
                int idx = tid + 256 * j;
                int m = idx >> 4, kk = idx & 15;
                As[nb][kk][m] = g_emb[(size_t)(bm + m) * DIM + k0 + 16 + kk];
            }
            #pragma unroll
            for (int j = 0; j < 8; j++) {
                int idx = tid + 256 * j;
                int kk = idx >> 7, n = idx & 127;
                Bs[nb][kk][n] = (n < CC) ? Wp[(size_t)(k0 + 16 + kk) * CC + n] : 0.f;
            }
        }
        #pragma unroll
        for (int kk = 0; kk < 16; kk++) {
            float a0 = As[buf][kk][tr * 4 + 0];
            float a1 = As[buf][kk][tr * 4 + 1];
            float a2 = As[buf][kk][tr * 4 + 2];
            float a3 = As[buf][kk][tr * 4 + 3];
            float4 b4 = *reinterpret_cast<const float4*>(&Bs[buf][kk][tc * 4]);
            acc[0][0] += a0 * b4.x; acc[0][1] += a0 * b4.y; acc[0][2] += a0 * b4.z; acc[0][3] += a0 * b4.w;
            acc[1][0] += a1 * b4.x; acc[1][1] += a1 * b4.y; acc[1][2] += a1 * b4.z; acc[1][3] += a1 * b4.w;
            acc[2][0] += a2 * b4.x; acc[2][1] += a2 * b4.y; acc[2][2] += a2 * b4.z; acc[2][3] += a2 * b4.w;
            acc[3][0] += a3 * b4.x; acc[3][1] += a3 * b4.y; acc[3][2] += a3 * b4.z; acc[3][3] += a3 * b4.w;
        }
        __syncthreads();
        buf = nb;
    }
    float entpart = 0.f;
    #pragma unroll
    for (int r = 0; r < 4; r++) {
        int row = bm + tr * 4 + r;
        float v[4];
        float mx = -1e30f;
        #pragma unroll
        for (int c = 0; c < 4; c++) {
            int n = tc * 4 + c;
            v[c] = (n < CC) ? (acc[r][c] + bp[n]) : -1e30f;
            mx = fmaxf(mx, v[c]);
        }
        #pragma unroll
        for (int o = 16; o > 0; o >>= 1) mx = fmaxf(mx, __shfl_xor_sync(0xffffffff, mx, o));
        float sm = 0.f;
        float ex[4];
        #pragma unroll
        for (int c = 0; c < 4; c++) {
            int n = tc * 4 + c;
            ex[c] = (n < CC) ? expf(v[c] - mx) : 0.f;
            sm += ex[c];
        }
        #pragma unroll
        for (int o = 16; o > 0; o >>= 1) sm += __shfl_xor_sync(0xffffffff, sm, o);
        float inv = 1.f / sm;
        #pragma unroll
        for (int c = 0; c < 4; c++) {
            int n = tc * 4 + c;
            if (n < CC) {
                float p = ex[c] * inv;
                g_sm[(size_t)row * CC + n] = p;
                entpart += -p * logf(p + 1e-15f);
            }
        }
    }
    #pragma unroll
    for (int o = 16; o > 0; o >>= 1) entpart += __shfl_xor_sync(0xffffffff, entpart, o);
    if (tc == 0) atomicAdd(&g_acc[2], entpart);
}

// ----------------------------- stage19: poolgram + cross + qp2 GEMM -------------------------------
// [0,192) poolgram | [192,6336) cross | [6336,6432) qp2
__global__ void k_stage19(const float* __restrict__ m2bi) {
    extern __shared__ float dyn[];      // poolgram staging: S[32][104] + E[32][128]
    __shared__ float shred[256];
    int b = blockIdx.x;
    int t = threadIdx.x;  // 256
    if (b < 192) {            // poolgram
        float* S_s = dyn;
        float* E_s = dyn + 32 * 104;
        int i0 = b * 32;
        for (int idx = t; idx < 32 * CC; idx += 256) {
            int r = idx / CC, c = idx % CC;
            S_s[r * 104 + c] = g_sm[(size_t)(i0 + r) * CC + c];
        }
        for (int idx = t; idx < 32 * DIM; idx += 256) {
            int r = idx >> 7, d = idx & 127;
            E_s[r * 128 + d] = g_emb[(size_t)(i0 + r) * DIM + d];
        }
        __syncthreads();
        for (int o = t; o < CC * 32; o += 256) {
            int c = o >> 5, d4 = o & 31;
            float4 a = make_float4(0.f, 0.f, 0.f, 0.f);
            for (int r = 0; r < 32; r++) {
                float s = S_s[r * 104 + c];
                float4 e4 = *reinterpret_cast<const float4*>(&E_s[r * 128 + d4 * 4]);
                a.x += s * e4.x; a.y += s * e4.y; a.z += s * e4.z; a.w += s * e4.w;
            }
            atomicAdd(&g_pooled[(size_t)c * DIM + d4 * 4 + 0], a.x);
            atomicAdd(&g_pooled[(size_t)c * DIM + d4 * 4 + 1], a.y);
            atomicAdd(&g_pooled[(size_t)c * DIM + d4 * 4 + 2], a.z);
            atomicAdd(&g_pooled[(size_t)c * DIM + d4 * 4 + 3], a.w);
        }
        for (int o = t; o < CC * 25; o += 256) {
            int c1 = o / 25, c2g = o % 25;
            float4 a = make_float4(0.f, 0.f, 0.f, 0.f);
            for (int r = 0; r < 32; r++) {
                float s = S_s[r * 104 + c1];
                float4 s4 = *reinterpret_cast<const float4*>(&S_s[r * 104 + c2g * 4]);
                a.x += s * s4.x; a.y += s * s4.y; a.z += s * s4.z; a.w += s * s4.w;
            }
            atomicAdd(&g_G[c1 * CC + c2g * 4 + 0], a.x);
            atomicAdd(&g_G[c1 * CC + c2g * 4 + 1], a.y);
            atomicAdd(&g_G[c1 * CC + c2g * 4 + 2], a.z);
            atomicAdd(&g_G[c1 * CC + c2g * 4 + 3], a.w);
        }
    } else if (b < 6336) {    // cross: <A,SS^T> via CSR gather + Adense scatter
        int q = b - 192;
        int beg = g_csr_off[q], end = g_csr_off[q + 1];
        float acc = 0.f;
        if (t < CC) {
            float tsum = 0.f;
            for (int j = beg; j < end; j++)
                tsum += g_csr_w[j] * g_sm[(size_t)g_csr_src[j] * CC + t];
            acc = tsum * g_sm[(size_t)q * CC + t];
        }
        float s = blockReduceSum(acc, shred);
        if (t == 0 && s != 0.f) atomicAdd(&g_acc[1], s);
        for (int j = beg + t; j < end; j += 256)
            atomicAdd(&g_Adense[(size_t)g_csr_src[j] * TWO_N + q], g_csr_w[j]);
    } else {                  // qp2 GEMM (96 blocks)
        sgemm_block(g_emb, g_wt, m2bi, g_qp2, TWO_N, DIM, DIM, DIM, DIM, b - 6336, 0);
    }
}

// ----------------------------- stage20: kvproj + normA (merged) -----------------------------------
__global__ void k_stage20(const float* __restrict__ wi, const float* __restrict__ bi,
                          const int* __restrict__ src, const int* __restrict__ dst) {
    int b = blockIdx.x;
    int t = threadIdx.x;  // 256
    if (b < 200) {
        __shared__ float prow[DIM];
        int c = b >> 1, which = b & 1;
        if (t < 128) prow[t] = g_pooled[(size_t)c * DIM + t];
        __syncthreads();
        if (t >= 128) return;
        const float4* row4 = reinterpret_cast<const float4*>(wi + (size_t)(DIM + which * DIM + t) * DIM);
        float acc = bi[DIM + which * DIM + t];
        #pragma unroll
        for (int k = 0; k < 32; k++) {
            float4 r = row4[k];
            acc += r.x * prow[4 * k] + r.y * prow[4 * k + 1]
                 + r.z * prow[4 * k + 2] + r.w * prow[4 * k + 3];
        }
        (which ? g_vp2 : g_kp2)[(size_t)c * DIM + t] = acc;
    } else {
        __shared__ float sh[256];
        int e = (b - 200) * 256 + t;
        float v = 0.f;
        if (e < EE) {
            float old = atomicExch(&g_Adense[(size_t)src[e] * TWO_N + dst[e]], 0.f);
            v = old * old;
        }
        float s = blockReduceSum(v, sh);
        if (t == 0 && s != 0.f) atomicAdd(&g_acc[0], s);
    }
}

// ----------------------------- stage21: mha2 (2 queries/iter, 256 thr) + gramfin ------------------
#define K_LD 129
__global__ void k_stage21(const float* __restrict__ wo, const float* __restrict__ bo,
                          float* __restrict__ out_skill, float* __restrict__ out_loss) {
    extern __shared__ float kp_s[];     // [CC][K_LD]
    int t = threadIdx.x;  // 256
    if (blockIdx.x == 384) {            // gramfin
        __shared__ float sh[256];
        float acc = 0.f;
        for (int i = t; i < CC * CC; i += 256) { float g = g_G[i]; acc += g * g; }
        float s = blockReduceSum(acc, sh);
        if (t == 0) {
            float n2 = g_acc[0] - 2.f * g_acc[1] + s;
            float link = sqrtf(fmaxf(n2, 0.f)) / ((float)TWO_N * (float)TWO_N);
            out_loss[0] = link + g_acc[2] / (float)TWO_N;
        }
        return;
    }
    __shared__ float qrow[2][DIM];
    __shared__ float lg[2][HH][CC];
    __shared__ float o_s[2][DIM];
    int g = t >> 7;            // query group 0/1
    int tg = t & 127;
    int w = tg >> 5, lane = tg & 31;
    for (int i = t; i < CC * DIM; i += 256) {
        int j = i >> 7, d = i & 127;
        kp_s[j * K_LD + d] = g_kp2[i];
    }
    __syncthreads();
    int n0 = blockIdx.x * 16;
    for (int q = 0; q < 16; q += 2) {
        int n = n0 + q + g;
        qrow[g][tg] = g_qp2[(size_t)n * DIM + tg];
        __syncthreads();
        for (int pos = tg; pos < HH * CC; pos += 128) {
            int h = pos / CC, j = pos % CC;
            float acc = 0.f;
            #pragma unroll 8
            for (int d = 0; d < HD; d++)
                acc += qrow[g][h * HD + d] * kp_s[j * K_LD + h * HD + d];
            lg[g][h][j] = acc * INV_SQRT_HD;
        }
        __syncthreads();
        {
            float mx = -1e30f;
            for (int j = lane; j < CC; j += 32) mx = fmaxf(mx, lg[g][w][j]);
            #pragma unroll
            for (int o = 16; o > 0; o >>= 1) mx = fmaxf(mx, __shfl_xor_sync(0xffffffff, mx, o));
            float sm = 0.f;
            for (int j = lane; j < CC; j += 32) { float e = expf(lg[g][w][j] - mx); lg[g][w][j] = e; sm += e; }
            #pragma unroll
            for (int o = 16; o > 0; o >>= 1) sm += __shfl_xor_sync(0xffffffff, sm, o);
            float inv = 1.f / sm;
            for (int j = lane; j < CC; j += 32) lg[g][w][j] *= inv;
        }
        __syncthreads();
        {
            float acc = 0.f;
            for (int j = 0; j < CC; j++) acc += lg[g][w][j] * g_vp2[(size_t)j * DIM + tg];
            o_s[g][tg] = acc;
        }
        __syncthreads();
        {
            const float4* row4 = reinterpret_cast<const float4*>(wo + (size_t)tg * DIM);
            float acc = bo[tg];
            #pragma unroll
            for (int k = 0; k < 32; k++) {
                float4 r = row4[k];
                acc += r.x * o_s[g][4 * k] + r.y * o_s[g][4 * k + 1]
                     + r.z * o_s[g][4 * k + 2] + r.w * o_s[g][4 * k + 3];
            }
            out_skill[(size_t)n * DIM + tg] = 2.f * g_emb[(size_t)n * DIM + tg] + acc;
        }
        __syncthreads();
    }
}

// ----------------------------- host launch -----------------------------
extern "C" void kernel_launch(void* const* d_in, const int* in_sizes, int n_in,
                              void* d_out, int out_size) {
    const float* demand = (const float*)d_in[0];
    const float* supply = (const float*)d_in[1];
    const float* skill  = (const float*)d_in[2];
    const int*   eidx   = (const int*)d_in[3];
    const float* eattr  = (const float*)d_in[4];
    const float* w_fuse = (const float*)d_in[5];
    const float* b_fuse = (const float*)d_in[6];
    const float* m1wi   = (const float*)d_in[7];
    const float* m1bi   = (const float*)d_in[8];
    const float* m1wo   = (const float*)d_in[9];
    const float* m1bo   = (const float*)d_in[10];
    const float* m2wi   = (const float*)d_in[11];
    const float* m2bi   = (const float*)d_in[12];
    const float* m2wo   = (const float*)d_in[13];
    const float* m2bo   = (const float*)d_in[14];
    const float* sender = (const float*)d_in[15];
    const float* recv   = (const float*)d_in[16];
    const float* W0     = (const float*)d_in[17];
    const float* b0     = (const float*)d_in[18];
    const float* W1     = (const float*)d_in[19];
    const float* b1     = (const float*)d_in[20];
    const float* Wp     = (const float*)d_in[21];
    const float* bp     = (const float*)d_in[22];
    float* out = (float*)d_out;
    const int* src = eidx;
    const int* dst = eidx + EE;

    cudaFuncSetAttribute(k_stage19, cudaFuncAttributeMaxDynamicSharedMemorySize,
                         (32 * 104 + 32 * 128) * (int)sizeof(float) + 1024);
    cudaFuncSetAttribute(k_stage21, cudaFuncAttributeMaxDynamicSharedMemorySize,
                         CC * K_LD * (int)sizeof(float) + 2048);

    float *p_cq, *p_wbig, *p_fb, *p_fused;
    cudaGetSymbolAddress((void**)&p_cq, g_cq);
    cudaGetSymbolAddress((void**)&p_wbig, g_wbig);
    cudaGetSymbolAddress((void**)&p_fb, g_fb);
    cudaGetSymbolAddress((void**)&p_fused, g_fused);

    k_init<<<64, 256>>>(sender, recv);
    k_stage1<<<3443, 256>>>(m1wi, m1wo, m1bo, m1bi, m2wi, demand, supply, dst, eattr,
                            out + OUT_PRED);
    k_stage2<<<769, 1024>>>(skill, out + OUT_CAT);
    k_stage3<<<457, 256>>>(w_fuse, b_fuse);
    k_attn1<<<TWO_N + 1536, 128>>>(demand, supply, src, dst, eattr);
    k_sgemm<<<dim3(1, 96), 256>>>(p_cq, p_wbig, p_fb, p_fused, TWO_N, DIM, 640, DIM);

    k_stage8<<<448, 256>>>(sender, recv, W0, W1);
    k_scores<<<1184, 256>>>();
    k_predg_general<<<TWO_N, 256>>>(out + OUT_PRED);
    k_dense_agg<<<TWO_N / 32, 256>>>();
    k_stage12<<<1536, 256>>>(b0, b1);
    k_stage13<<<192, 256>>>(W0, W1);
    k_dense_agg<<<TWO_N / 32, 256>>>();
    k_stage16<<<768, 256>>>(b0, b1);

    k_sm_gemm<<<192, 256>>>(Wp, bp);
    k_stage19<<<6432, 256, (32 * 104 + 32 * 128) * sizeof(float)>>>(m2bi);
    k_stage20<<<968, 256>>>(m2wi, m2bi, src, dst);
    k_stage21<<<385, 256, CC * K_LD * sizeof(float) + 2048>>>(m2wo, m2bo, out + OUT_SKILL, out + OUT_LOSS);
}